// round 1
// baseline (speedup 1.0000x reference)
#include <cuda_runtime.h>
#include <cstddef>

// ---------------------------------------------------------------------------
// Seq2Seq LSTM (2-layer encoder T=50, 2-layer decoder T=60), H=128, B=16384.
//
// Strategy: batch elements are fully independent. Each CTA owns S_TILE=32
// batch samples and runs the ENTIRE 110-step recurrence locally:
//   - h0/h1 state in SMEM, c0/c1 state in registers
//   - decoder initial state = encoder final state (per reference semantics)
//   - the big 512x128 weight matrices are streamed from L2 each step through
//     an SMEM staging tile (K-tiled, KT=16, padded stride for conflict-free LDS)
//   - small weights (enc_Wih0 512x6, dec_Wih0 512x2, out_W, biases, start
//     token) are persisted in SMEM once.
//
// Thread layout: 256 threads = 2 sample-groups x 128 gate lanes.
// Lane j computes gate rows {j, j+128, j+256, j+384} (i,f,g,o) for its
// group's SG=16 samples. acc[4][16] registers, fp32 throughout.
// ---------------------------------------------------------------------------

#define THREADS 256
#define SG      16              // samples per group
#define S_TILE  32              // samples per CTA (2 groups)
#define KT      16              // K tile for weight staging
#define WSTR    (KT + 1)        // padded SMEM stride -> conflict-free LDS

constexpr int H      = 128;
constexpr int G4     = 512;     // 4*H gate rows
constexpr int INF    = 6;
constexpr int OUTF   = 2;
constexpr int T_HIST = 50;
constexpr int T_OUT  = 60;
constexpr int A_     = 8;
constexpr int B_     = 16384;

struct Smem {
  float w[G4 * WSTR];        // staged weight tile       (34816 B)
  float h0[S_TILE * H];      // layer-0 hidden state     (16384 B)
  float h1[S_TILE * H];      // layer-1 hidden state     (16384 B)
  float x[S_TILE * 8];       // current input (padded to 8)
  float wih0e[G4 * 8];       // enc_Wih0 (512x6, padded to 8)
  float wih0d[G4 * 4];       // dec_Wih0 (512x2, padded to 4)
  float outW[2 * H];
  float b[4 * G4];           // enc_b0 | enc_b1 | dec_b0 | dec_b1
  float outb[2];
  float st[2];               // start token
};

__device__ __forceinline__ float sigmoidf_(float v) {
  return 1.0f / (1.0f + __expf(-v));
}
__device__ __forceinline__ float tanhf_(float v) {
  // tanh via exp of -2|x| to avoid overflow; exact sign handling.
  float ax = fabsf(v);
  float e  = __expf(-2.0f * ax);
  float r  = __fdividef(1.0f - e, 1.0f + e);
  return copysignf(r, v);
}

__device__ __forceinline__ void init_acc(float (&acc)[4][SG], const float* bptr, int j) {
#pragma unroll
  for (int g = 0; g < 4; ++g) {
    float bv = bptr[g * H + j];
#pragma unroll
    for (int k = 0; k < SG; ++k) acc[g][k] = bv;
  }
}

// acc += W[:, :] @ src  for this thread's 4 gate rows and SG samples.
// W is a global 512x128 row-major matrix, staged through s.w in KT-column tiles.
__device__ __forceinline__ void accum128(float (&acc)[4][SG],
                                         const float* __restrict__ Wg,
                                         const float* __restrict__ src,  // [S_TILE][H] in SMEM
                                         float* __restrict__ wsm,
                                         int j, int s0, int tid) {
  for (int k0 = 0; k0 < H; k0 += KT) {
    __syncthreads();  // prior tile compute (or prior writers of src) done
    // stage 512 x KT tile, float4 global loads, scalar SMEM stores (padded)
    for (int idx = tid; idx < G4 * (KT / 4); idx += THREADS) {
      int r  = idx >> 2;          // KT/4 == 4
      int c4 = (idx & 3) << 2;
      float4 v = *reinterpret_cast<const float4*>(Wg + r * H + k0 + c4);
      float* dst = wsm + r * WSTR + c4;
      dst[0] = v.x; dst[1] = v.y; dst[2] = v.z; dst[3] = v.w;
    }
    __syncthreads();
#pragma unroll
    for (int c = 0; c < KT; ++c) {
      float wi = wsm[(j      ) * WSTR + c];
      float wf = wsm[(j + 128) * WSTR + c];
      float wg = wsm[(j + 256) * WSTR + c];
      float wo = wsm[(j + 384) * WSTR + c];
#pragma unroll
      for (int k = 0; k < SG; ++k) {
        float hv = src[(s0 + k) * H + k0 + c];   // broadcast across lanes
        acc[0][k] = fmaf(wi, hv, acc[0][k]);
        acc[1][k] = fmaf(wf, hv, acc[1][k]);
        acc[2][k] = fmaf(wg, hv, acc[2][k]);
        acc[3][k] = fmaf(wo, hv, acc[3][k]);
      }
    }
  }
}

__device__ __forceinline__ void cell_update(float (&acc)[4][SG], float* cr, float* hnew) {
#pragma unroll
  for (int k = 0; k < SG; ++k) {
    float iv = sigmoidf_(acc[0][k]);
    float fv = sigmoidf_(acc[1][k]);
    float gv = tanhf_(acc[2][k]);
    float ov = sigmoidf_(acc[3][k]);
    float c  = fv * cr[k] + iv * gv;
    cr[k]    = c;
    hnew[k]  = ov * tanhf_(c);
  }
}

__device__ __forceinline__ void write_h(float* hdst, const float* hnew, int j, int s0) {
#pragma unroll
  for (int k = 0; k < SG; ++k) hdst[(s0 + k) * H + j] = hnew[k];
}

__global__ void __launch_bounds__(THREADS)
lstm_seq2seq_kernel(const float* __restrict__ history,
                    const float* __restrict__ start_token,
                    const float* __restrict__ eWih0, const float* __restrict__ eWhh0,
                    const float* __restrict__ eb0,
                    const float* __restrict__ eWih1, const float* __restrict__ eWhh1,
                    const float* __restrict__ eb1,
                    const float* __restrict__ dWih0, const float* __restrict__ dWhh0,
                    const float* __restrict__ db0,
                    const float* __restrict__ dWih1, const float* __restrict__ dWhh1,
                    const float* __restrict__ db1,
                    const float* __restrict__ outW, const float* __restrict__ outb,
                    float* __restrict__ out) {
  extern __shared__ float smraw[];
  Smem& s = *reinterpret_cast<Smem*>(smraw);

  const int tid = threadIdx.x;
  const int j   = tid & 127;      // gate lane / hidden unit
  const int grp = tid >> 7;       // sample group (0,1)
  const int s0  = grp * SG;
  const int b0  = blockIdx.x * S_TILE;

  // ---- persistent SMEM loads (once) ----
  for (int idx = tid; idx < G4 * INF; idx += THREADS) {
    int r = idx / INF, c = idx % INF;
    s.wih0e[r * 8 + c] = eWih0[idx];
  }
  for (int idx = tid; idx < G4 * OUTF; idx += THREADS) {
    int r = idx >> 1, c = idx & 1;
    s.wih0d[r * 4 + c] = dWih0[idx];
  }
  for (int idx = tid; idx < 2 * H; idx += THREADS) s.outW[idx] = outW[idx];
  for (int idx = tid; idx < G4; idx += THREADS) {
    s.b[idx]            = eb0[idx];
    s.b[G4 + idx]       = eb1[idx];
    s.b[2 * G4 + idx]   = db0[idx];
    s.b[3 * G4 + idx]   = db1[idx];
  }
  if (tid < 2) { s.outb[tid] = outb[tid]; s.st[tid] = start_token[tid]; }
  for (int idx = tid; idx < S_TILE * H; idx += THREADS) { s.h0[idx] = 0.0f; s.h1[idx] = 0.0f; }

  float c0r[SG], c1r[SG];
#pragma unroll
  for (int k = 0; k < SG; ++k) { c0r[k] = 0.0f; c1r[k] = 0.0f; }

  float acc[4][SG];
  float hnew[SG];

  __syncthreads();

  // ================= ENCODER =================
  for (int t = 0; t < T_HIST; ++t) {
    // load ego input x_t (agent 0)
    if (tid < S_TILE * INF) {
      int ss = tid / INF, i = tid % INF;
      s.x[ss * 8 + i] =
          history[(((size_t)(b0 + ss) * A_ + 0) * T_HIST + t) * INF + i];
    }
    __syncthreads();

    // ---- layer 0: gates = eWih0 @ x + eWhh0 @ h0 + eb0 ----
    init_acc(acc, &s.b[0], j);
#pragma unroll
    for (int i = 0; i < INF; ++i) {
      float wi = s.wih0e[(j      ) * 8 + i];
      float wf = s.wih0e[(j + 128) * 8 + i];
      float wg = s.wih0e[(j + 256) * 8 + i];
      float wo = s.wih0e[(j + 384) * 8 + i];
#pragma unroll
      for (int k = 0; k < SG; ++k) {
        float xv = s.x[(s0 + k) * 8 + i];
        acc[0][k] = fmaf(wi, xv, acc[0][k]);
        acc[1][k] = fmaf(wf, xv, acc[1][k]);
        acc[2][k] = fmaf(wg, xv, acc[2][k]);
        acc[3][k] = fmaf(wo, xv, acc[3][k]);
      }
    }
    accum128(acc, eWhh0, s.h0, s.w, j, s0, tid);
    cell_update(acc, c0r, hnew);
    __syncthreads();               // all reads of old h0 done
    write_h(s.h0, hnew, j, s0);
    __syncthreads();

    // ---- layer 1: gates = eWih1 @ h0_new + eWhh1 @ h1 + eb1 ----
    init_acc(acc, &s.b[G4], j);
    accum128(acc, eWih1, s.h0, s.w, j, s0, tid);
    accum128(acc, eWhh1, s.h1, s.w, j, s0, tid);
    cell_update(acc, c1r, hnew);
    __syncthreads();
    write_h(s.h1, hnew, j, s0);
    __syncthreads();
  }

  // decoder input x0 = start token (broadcast)
  if (tid < S_TILE * OUTF) {
    int ss = tid >> 1, o = tid & 1;
    s.x[ss * 8 + o] = s.st[o];
  }
  __syncthreads();

  // ================= DECODER =================
  // carries over (h0,c0) and (h1,c1) from the encoder final state.
  for (int t = 0; t < T_OUT; ++t) {
    // ---- layer 0: gates = dWih0 @ x + dWhh0 @ h0 + db0 ----
    init_acc(acc, &s.b[2 * G4], j);
#pragma unroll
    for (int i = 0; i < OUTF; ++i) {
      float wi = s.wih0d[(j      ) * 4 + i];
      float wf = s.wih0d[(j + 128) * 4 + i];
      float wg = s.wih0d[(j + 256) * 4 + i];
      float wo = s.wih0d[(j + 384) * 4 + i];
#pragma unroll
      for (int k = 0; k < SG; ++k) {
        float xv = s.x[(s0 + k) * 8 + i];
        acc[0][k] = fmaf(wi, xv, acc[0][k]);
        acc[1][k] = fmaf(wf, xv, acc[1][k]);
        acc[2][k] = fmaf(wg, xv, acc[2][k]);
        acc[3][k] = fmaf(wo, xv, acc[3][k]);
      }
    }
    accum128(acc, dWhh0, s.h0, s.w, j, s0, tid);
    cell_update(acc, c0r, hnew);
    __syncthreads();
    write_h(s.h0, hnew, j, s0);
    __syncthreads();

    // ---- layer 1: gates = dWih1 @ h0_new + dWhh1 @ h1 + db1 ----
    init_acc(acc, &s.b[3 * G4], j);
    accum128(acc, dWih1, s.h0, s.w, j, s0, tid);
    accum128(acc, dWhh1, s.h1, s.w, j, s0, tid);
    cell_update(acc, c1r, hnew);
    __syncthreads();
    write_h(s.h1, hnew, j, s0);
    __syncthreads();

    // ---- projection: y = h1 @ outW^T + outb; feed back as next x ----
    if (tid < S_TILE * OUTF) {
      int ss = tid >> 1, o = tid & 1;
      float a = s.outb[o];
      const float* wrow = &s.outW[o * H];
      const float* hrow = &s.h1[ss * H];
#pragma unroll 16
      for (int k = 0; k < H; ++k) a = fmaf(wrow[k], hrow[k], a);
      out[((size_t)(b0 + ss) * T_OUT + t) * OUTF + o] = a;
      s.x[ss * 8 + o] = a;
    }
    __syncthreads();
  }
}

extern "C" void kernel_launch(void* const* d_in, const int* in_sizes, int n_in,
                              void* d_out, int out_size) {
  const float* history     = (const float*)d_in[0];
  const float* start_token = (const float*)d_in[1];
  const float* eWih0       = (const float*)d_in[2];
  const float* eWhh0       = (const float*)d_in[3];
  const float* eb0         = (const float*)d_in[4];
  const float* eWih1       = (const float*)d_in[5];
  const float* eWhh1       = (const float*)d_in[6];
  const float* eb1         = (const float*)d_in[7];
  const float* dWih0       = (const float*)d_in[8];
  const float* dWhh0       = (const float*)d_in[9];
  const float* db0         = (const float*)d_in[10];
  const float* dWih1       = (const float*)d_in[11];
  const float* dWhh1       = (const float*)d_in[12];
  const float* db1         = (const float*)d_in[13];
  const float* outW        = (const float*)d_in[14];
  const float* outb        = (const float*)d_in[15];
  float* out               = (float*)d_out;

  (void)in_sizes; (void)n_in; (void)out_size;

  cudaFuncSetAttribute(lstm_seq2seq_kernel,
                       cudaFuncAttributeMaxDynamicSharedMemorySize,
                       (int)sizeof(Smem));

  dim3 grid(B_ / S_TILE);   // 512 CTAs, each owns 32 batch samples
  lstm_seq2seq_kernel<<<grid, THREADS, sizeof(Smem)>>>(
      history, start_token,
      eWih0, eWhh0, eb0, eWih1, eWhh1, eb1,
      dWih0, dWhh0, db0, dWih1, dWhh1, db1,
      outW, outb, out);
}

// round 2
// speedup vs baseline: 1.1601x; 1.1601x over previous
#include <cuda_runtime.h>
#include <cstddef>

// ---------------------------------------------------------------------------
// Seq2Seq LSTM, round 2: packed fp32x2 FFMA + transposed hidden state +
// double-buffered weight staging.
//
// Each CTA owns S_TILE=32 batch samples, runs all 110 recurrence steps.
// 256 threads = 2 sample-groups x 128 gate lanes. Lane j computes gate rows
// {j, j+128, j+256, j+384}; samples are processed in PAIRS packed into
// 64-bit registers driven by fma.rn.f32x2 (2 fp32 MACs per issue slot).
//
// Hidden state is stored transposed in SMEM: hT[hidden][sample] with a
// 36-float row stride (rows 16B-aligned, sample pairs contiguous ->
// broadcast LDS.128 on the read side, 4-way-conflict STS.128 on the rare
// write side).
//
// The 512x128 weight matrices are streamed from L2 each step through a
// double-buffered SMEM tile: LDG of tile k+1 (registers) overlaps compute
// of tile k; one __syncthreads per tile.
// ---------------------------------------------------------------------------

#define THREADS 256
#define SG      16              // samples per group (8 pairs)
#define S_TILE  32              // samples per CTA
#define KT      16              // K tile for weight staging
#define WSTR    (KT + 1)        // padded stride, conflict-free scalar LDS
#define HSTR    36              // transposed-h row stride (16B aligned rows)

constexpr int H      = 128;
constexpr int G4     = 512;
constexpr int INF    = 6;
constexpr int OUTF   = 2;
constexpr int T_HIST = 50;
constexpr int T_OUT  = 60;
constexpr int A_     = 8;
constexpr int B_     = 16384;

typedef unsigned long long ull;

struct Smem {
  float w2[2 * G4 * WSTR];   // double-buffered weight tile (69632 B)
  float hT0[H * HSTR];       // layer-0 hidden, transposed  (18432 B)
  float hT1[H * HSTR];       // layer-1 hidden, transposed  (18432 B)
  float xT[8 * S_TILE];      // input, transposed [feat][sample] (1024 B)
  float wih0e[G4 * 8];       // enc_Wih0 512x6 padded       (16384 B)
  float wih0d[G4 * 4];       // dec_Wih0 512x2 padded       (8192 B)
  float outW[2 * H];
  float b[4 * G4];           // eb0 | eb1 | db0 | db1
  float outb[4];
  float st[4];
};

// ---- fp32x2 helpers -------------------------------------------------------
__device__ __forceinline__ ull pack2(float v) {
  ull r; unsigned u = __float_as_uint(v);
  asm("mov.b64 %0, {%1, %1};" : "=l"(r) : "r"(u));
  return r;
}
__device__ __forceinline__ void unpack2(ull v, float& lo, float& hi) {
  unsigned a, b;
  asm("mov.b64 {%0, %1}, %2;" : "=r"(a), "=r"(b) : "l"(v));
  lo = __uint_as_float(a); hi = __uint_as_float(b);
}
__device__ __forceinline__ void ffma2(ull& d, ull a, ull b) {
  asm("fma.rn.f32x2 %0, %1, %2, %0;" : "+l"(d) : "l"(a), "l"(b));
}

__device__ __forceinline__ float sigmoidf_(float v) {
  return 1.0f / (1.0f + __expf(-v));
}
__device__ __forceinline__ float tanhf_(float v) {
  float ax = fabsf(v);
  float e  = __expf(-2.0f * ax);
  float r  = __fdividef(1.0f - e, 1.0f + e);
  return copysignf(r, v);
}

__device__ __forceinline__ void init_acc(ull (&acc)[4][8], const float* bptr, int j) {
#pragma unroll
  for (int g = 0; g < 4; ++g) {
    ull bv = pack2(bptr[g * H + j]);
#pragma unroll
    for (int p = 0; p < 8; ++p) acc[g][p] = bv;
  }
}

// ---- weight staging (register double buffer across KT tiles) --------------
__device__ __forceinline__ void stage_ldg(float4 (&r)[8], const float* __restrict__ Wg,
                                          int k0, int tid) {
#pragma unroll
  for (int u = 0; u < 8; ++u) {
    int idx = tid + u * THREADS;          // 0..2047 covers 512 rows x 16 cols
    int row = idx >> 2;
    int c4  = (idx & 3) << 2;
    r[u] = *reinterpret_cast<const float4*>(Wg + row * H + k0 + c4);
  }
}
__device__ __forceinline__ void stage_sts(const float4 (&r)[8], float* wb, int tid) {
#pragma unroll
  for (int u = 0; u < 8; ++u) {
    int idx = tid + u * THREADS;
    int row = idx >> 2;
    int c4  = (idx & 3) << 2;
    float* d = wb + row * WSTR + c4;
    d[0] = r[u].x; d[1] = r[u].y; d[2] = r[u].z; d[3] = r[u].w;
  }
}

// acc += W @ srcT for this thread's 4 gate rows and 8 sample pairs.
__device__ __forceinline__ void accum128(ull (&acc)[4][8],
                                         const float* __restrict__ Wg,
                                         const float* __restrict__ srcT,
                                         float* __restrict__ wbuf,
                                         int j, int s0, int tid) {
  float4 r[8];
  stage_ldg(r, Wg, 0, tid);
  __syncthreads();                      // prior readers of wbuf are done
  int cur = 0;
#pragma unroll 1
  for (int t8 = 0; t8 < 8; ++t8) {
    stage_sts(r, wbuf + cur * (G4 * WSTR), tid);
    __syncthreads();
    if (t8 < 7) stage_ldg(r, Wg, (t8 + 1) * KT, tid);   // overlap next tile
    const float* wb = wbuf + cur * (G4 * WSTR);
    const int k0 = t8 * KT;
#pragma unroll
    for (int c = 0; c < KT; ++c) {
      const float* hrow = srcT + (k0 + c) * HSTR + s0;
      ulonglong2 a0 = *reinterpret_cast<const ulonglong2*>(hrow);
      ulonglong2 a1 = *reinterpret_cast<const ulonglong2*>(hrow + 4);
      ulonglong2 a2 = *reinterpret_cast<const ulonglong2*>(hrow + 8);
      ulonglong2 a3 = *reinterpret_cast<const ulonglong2*>(hrow + 12);
      ull hp0 = a0.x, hp1 = a0.y, hp2 = a1.x, hp3 = a1.y;
      ull hp4 = a2.x, hp5 = a2.y, hp6 = a3.x, hp7 = a3.y;
#pragma unroll
      for (int g = 0; g < 4; ++g) {
        ull w = pack2(wb[(j + (g << 7)) * WSTR + c]);
        ffma2(acc[g][0], w, hp0); ffma2(acc[g][1], w, hp1);
        ffma2(acc[g][2], w, hp2); ffma2(acc[g][3], w, hp3);
        ffma2(acc[g][4], w, hp4); ffma2(acc[g][5], w, hp5);
        ffma2(acc[g][6], w, hp6); ffma2(acc[g][7], w, hp7);
      }
    }
    cur ^= 1;
  }
}

// small input contribution (nf features) from transposed xT using packed pairs
__device__ __forceinline__ void accum_small(ull (&acc)[4][8],
                                            const float* __restrict__ wsm, int wstr,
                                            const float* __restrict__ xT, int nf,
                                            int j, int s0) {
  for (int i = 0; i < nf; ++i) {
    const float* xrow = xT + i * S_TILE + s0;
    ulonglong2 a0 = *reinterpret_cast<const ulonglong2*>(xrow);
    ulonglong2 a1 = *reinterpret_cast<const ulonglong2*>(xrow + 4);
    ulonglong2 a2 = *reinterpret_cast<const ulonglong2*>(xrow + 8);
    ulonglong2 a3 = *reinterpret_cast<const ulonglong2*>(xrow + 12);
    ull hp[8] = {a0.x, a0.y, a1.x, a1.y, a2.x, a2.y, a3.x, a3.y};
#pragma unroll
    for (int g = 0; g < 4; ++g) {
      ull w = pack2(wsm[(j + (g << 7)) * wstr + i]);
#pragma unroll
      for (int p = 0; p < 8; ++p) ffma2(acc[g][p], w, hp[p]);
    }
  }
}

__device__ __forceinline__ void cell_update(ull (&acc)[4][8], float* cr, float* hnew) {
#pragma unroll
  for (int p = 0; p < 8; ++p) {
    float i0, i1, f0, f1, g0, g1, o0, o1;
    unpack2(acc[0][p], i0, i1);
    unpack2(acc[1][p], f0, f1);
    unpack2(acc[2][p], g0, g1);
    unpack2(acc[3][p], o0, o1);
    float c0 = sigmoidf_(f0) * cr[2 * p]     + sigmoidf_(i0) * tanhf_(g0);
    float c1 = sigmoidf_(f1) * cr[2 * p + 1] + sigmoidf_(i1) * tanhf_(g1);
    cr[2 * p]     = c0;
    cr[2 * p + 1] = c1;
    hnew[2 * p]     = sigmoidf_(o0) * tanhf_(c0);
    hnew[2 * p + 1] = sigmoidf_(o1) * tanhf_(c1);
  }
}

__device__ __forceinline__ void write_h(float* hT, const float* hnew, int j, int s0) {
  float* base = hT + j * HSTR + s0;
#pragma unroll
  for (int m = 0; m < 4; ++m) {
    *reinterpret_cast<float4*>(base + 4 * m) =
        make_float4(hnew[4 * m], hnew[4 * m + 1], hnew[4 * m + 2], hnew[4 * m + 3]);
  }
}

__global__ void __launch_bounds__(THREADS)
lstm_seq2seq_kernel(const float* __restrict__ history,
                    const float* __restrict__ start_token,
                    const float* __restrict__ eWih0, const float* __restrict__ eWhh0,
                    const float* __restrict__ eb0,
                    const float* __restrict__ eWih1, const float* __restrict__ eWhh1,
                    const float* __restrict__ eb1,
                    const float* __restrict__ dWih0, const float* __restrict__ dWhh0,
                    const float* __restrict__ db0,
                    const float* __restrict__ dWih1, const float* __restrict__ dWhh1,
                    const float* __restrict__ db1,
                    const float* __restrict__ outW, const float* __restrict__ outb,
                    float* __restrict__ out) {
  extern __shared__ float smraw[];
  Smem& s = *reinterpret_cast<Smem*>(smraw);

  const int tid = threadIdx.x;
  const int j   = tid & 127;
  const int s0  = (tid >> 7) * SG;
  const int b0  = blockIdx.x * S_TILE;

  // ---- one-time SMEM setup ----
  for (int idx = tid; idx < G4 * INF; idx += THREADS) {
    int r = idx / INF, c = idx % INF;
    s.wih0e[r * 8 + c] = eWih0[idx];
  }
  for (int idx = tid; idx < G4 * OUTF; idx += THREADS) {
    int r = idx >> 1, c = idx & 1;
    s.wih0d[r * 4 + c] = dWih0[idx];
  }
  for (int idx = tid; idx < 2 * H; idx += THREADS) s.outW[idx] = outW[idx];
  for (int idx = tid; idx < G4; idx += THREADS) {
    s.b[idx]          = eb0[idx];
    s.b[G4 + idx]     = eb1[idx];
    s.b[2 * G4 + idx] = db0[idx];
    s.b[3 * G4 + idx] = db1[idx];
  }
  if (tid < 2) { s.outb[tid] = outb[tid]; s.st[tid] = start_token[tid]; }
  for (int idx = tid; idx < H * HSTR; idx += THREADS) { s.hT0[idx] = 0.0f; s.hT1[idx] = 0.0f; }

  float c0r[SG], c1r[SG];
#pragma unroll
  for (int k = 0; k < SG; ++k) { c0r[k] = 0.0f; c1r[k] = 0.0f; }

  ull  acc[4][8];
  float hnew[SG];

  __syncthreads();

  // ================= ENCODER =================
  for (int t = 0; t < T_HIST; ++t) {
    if (tid < S_TILE * INF) {
      int ss = tid / INF, i = tid % INF;
      s.xT[i * S_TILE + ss] =
          history[(((size_t)(b0 + ss) * A_ + 0) * T_HIST + t) * INF + i];
    }
    __syncthreads();

    // layer 0
    init_acc(acc, &s.b[0], j);
    accum_small(acc, s.wih0e, 8, s.xT, INF, j, s0);
    accum128(acc, eWhh0, s.hT0, s.w2, j, s0, tid);
    cell_update(acc, c0r, hnew);
    __syncthreads();                 // readers of old hT0 done
    write_h(s.hT0, hnew, j, s0);
    __syncthreads();

    // layer 1
    init_acc(acc, &s.b[G4], j);
    accum128(acc, eWih1, s.hT0, s.w2, j, s0, tid);
    accum128(acc, eWhh1, s.hT1, s.w2, j, s0, tid);
    cell_update(acc, c1r, hnew);
    __syncthreads();
    write_h(s.hT1, hnew, j, s0);
    __syncthreads();
  }

  // decoder start token
  if (tid < S_TILE * OUTF) {
    int ss = tid >> 1, o = tid & 1;
    s.xT[o * S_TILE + ss] = s.st[o];
  }
  __syncthreads();

  // ================= DECODER =================
  for (int t = 0; t < T_OUT; ++t) {
    // layer 0
    init_acc(acc, &s.b[2 * G4], j);
    accum_small(acc, s.wih0d, 4, s.xT, OUTF, j, s0);
    accum128(acc, dWhh0, s.hT0, s.w2, j, s0, tid);
    cell_update(acc, c0r, hnew);
    __syncthreads();
    write_h(s.hT0, hnew, j, s0);
    __syncthreads();

    // layer 1
    init_acc(acc, &s.b[3 * G4], j);
    accum128(acc, dWih1, s.hT0, s.w2, j, s0, tid);
    accum128(acc, dWhh1, s.hT1, s.w2, j, s0, tid);
    cell_update(acc, c1r, hnew);
    __syncthreads();
    write_h(s.hT1, hnew, j, s0);
    __syncthreads();

    // projection + feedback
    if (tid < S_TILE * OUTF) {
      int ss = tid >> 1, o = tid & 1;
      float a = s.outb[o];
      const float* wrow = &s.outW[o * H];
#pragma unroll 16
      for (int k = 0; k < H; ++k) a = fmaf(wrow[k], s.hT1[k * HSTR + ss], a);
      out[((size_t)(b0 + ss) * T_OUT + t) * OUTF + o] = a;
      s.xT[o * S_TILE + ss] = a;
    }
    __syncthreads();
  }
}

extern "C" void kernel_launch(void* const* d_in, const int* in_sizes, int n_in,
                              void* d_out, int out_size) {
  const float* history     = (const float*)d_in[0];
  const float* start_token = (const float*)d_in[1];
  const float* eWih0       = (const float*)d_in[2];
  const float* eWhh0       = (const float*)d_in[3];
  const float* eb0         = (const float*)d_in[4];
  const float* eWih1       = (const float*)d_in[5];
  const float* eWhh1       = (const float*)d_in[6];
  const float* eb1         = (const float*)d_in[7];
  const float* dWih0       = (const float*)d_in[8];
  const float* dWhh0       = (const float*)d_in[9];
  const float* db0         = (const float*)d_in[10];
  const float* dWih1       = (const float*)d_in[11];
  const float* dWhh1       = (const float*)d_in[12];
  const float* db1         = (const float*)d_in[13];
  const float* outW        = (const float*)d_in[14];
  const float* outb        = (const float*)d_in[15];
  float* out               = (float*)d_out;

  (void)in_sizes; (void)n_in; (void)out_size;

  cudaFuncSetAttribute(lstm_seq2seq_kernel,
                       cudaFuncAttributeMaxDynamicSharedMemorySize,
                       (int)sizeof(Smem));

  dim3 grid(B_ / S_TILE);   // 512 CTAs
  lstm_seq2seq_kernel<<<grid, THREADS, sizeof(Smem)>>>(
      history, start_token,
      eWih0, eWhh0, eb0, eWih1, eWhh1, eb1,
      dWih0, dWhh0, db0, dWih1, dWhh1, db1,
      outW, outb, out);
}

// round 3
// speedup vs baseline: 1.1611x; 1.0009x over previous
#include <cuda_runtime.h>
#include <cstddef>

// ---------------------------------------------------------------------------
// Seq2Seq LSTM, round 2: packed fp32x2 FFMA + transposed hidden state +
// double-buffered weight staging.
//
// Each CTA owns S_TILE=32 batch samples, runs all 110 recurrence steps.
// 256 threads = 2 sample-groups x 128 gate lanes. Lane j computes gate rows
// {j, j+128, j+256, j+384}; samples are processed in PAIRS packed into
// 64-bit registers driven by fma.rn.f32x2 (2 fp32 MACs per issue slot).
//
// Hidden state is stored transposed in SMEM: hT[hidden][sample] with a
// 36-float row stride (rows 16B-aligned, sample pairs contiguous ->
// broadcast LDS.128 on the read side, 4-way-conflict STS.128 on the rare
// write side).
//
// The 512x128 weight matrices are streamed from L2 each step through a
// double-buffered SMEM tile: LDG of tile k+1 (registers) overlaps compute
// of tile k; one __syncthreads per tile.
// ---------------------------------------------------------------------------

#define THREADS 256
#define SG      16              // samples per group (8 pairs)
#define S_TILE  32              // samples per CTA
#define KT      16              // K tile for weight staging
#define WSTR    (KT + 1)        // padded stride, conflict-free scalar LDS
#define HSTR    36              // transposed-h row stride (16B aligned rows)

constexpr int H      = 128;
constexpr int G4     = 512;
constexpr int INF    = 6;
constexpr int OUTF   = 2;
constexpr int T_HIST = 50;
constexpr int T_OUT  = 60;
constexpr int A_     = 8;
constexpr int B_     = 16384;

typedef unsigned long long ull;

struct Smem {
  float w2[2 * G4 * WSTR];   // double-buffered weight tile (69632 B)
  float hT0[H * HSTR];       // layer-0 hidden, transposed  (18432 B)
  float hT1[H * HSTR];       // layer-1 hidden, transposed  (18432 B)
  float xT[8 * S_TILE];      // input, transposed [feat][sample] (1024 B)
  float wih0e[G4 * 8];       // enc_Wih0 512x6 padded       (16384 B)
  float wih0d[G4 * 4];       // dec_Wih0 512x2 padded       (8192 B)
  float outW[2 * H];
  float b[4 * G4];           // eb0 | eb1 | db0 | db1
  float outb[4];
  float st[4];
};

// ---- fp32x2 helpers -------------------------------------------------------
__device__ __forceinline__ ull pack2(float v) {
  ull r; unsigned u = __float_as_uint(v);
  asm("mov.b64 %0, {%1, %1};" : "=l"(r) : "r"(u));
  return r;
}
__device__ __forceinline__ void unpack2(ull v, float& lo, float& hi) {
  unsigned a, b;
  asm("mov.b64 {%0, %1}, %2;" : "=r"(a), "=r"(b) : "l"(v));
  lo = __uint_as_float(a); hi = __uint_as_float(b);
}
__device__ __forceinline__ void ffma2(ull& d, ull a, ull b) {
  asm("fma.rn.f32x2 %0, %1, %2, %0;" : "+l"(d) : "l"(a), "l"(b));
}

__device__ __forceinline__ float sigmoidf_(float v) {
  return 1.0f / (1.0f + __expf(-v));
}
__device__ __forceinline__ float tanhf_(float v) {
  float ax = fabsf(v);
  float e  = __expf(-2.0f * ax);
  float r  = __fdividef(1.0f - e, 1.0f + e);
  return copysignf(r, v);
}

__device__ __forceinline__ void init_acc(ull (&acc)[4][8], const float* bptr, int j) {
#pragma unroll
  for (int g = 0; g < 4; ++g) {
    ull bv = pack2(bptr[g * H + j]);
#pragma unroll
    for (int p = 0; p < 8; ++p) acc[g][p] = bv;
  }
}

// ---- weight staging (register double buffer across KT tiles) --------------
__device__ __forceinline__ void stage_ldg(float4 (&r)[8], const float* __restrict__ Wg,
                                          int k0, int tid) {
#pragma unroll
  for (int u = 0; u < 8; ++u) {
    int idx = tid + u * THREADS;          // 0..2047 covers 512 rows x 16 cols
    int row = idx >> 2;
    int c4  = (idx & 3) << 2;
    r[u] = *reinterpret_cast<const float4*>(Wg + row * H + k0 + c4);
  }
}
__device__ __forceinline__ void stage_sts(const float4 (&r)[8], float* wb, int tid) {
#pragma unroll
  for (int u = 0; u < 8; ++u) {
    int idx = tid + u * THREADS;
    int row = idx >> 2;
    int c4  = (idx & 3) << 2;
    float* d = wb + row * WSTR + c4;
    d[0] = r[u].x; d[1] = r[u].y; d[2] = r[u].z; d[3] = r[u].w;
  }
}

// acc += W @ srcT for this thread's 4 gate rows and 8 sample pairs.
__device__ __forceinline__ void accum128(ull (&acc)[4][8],
                                         const float* __restrict__ Wg,
                                         const float* __restrict__ srcT,
                                         float* __restrict__ wbuf,
                                         int j, int s0, int tid) {
  float4 r[8];
  stage_ldg(r, Wg, 0, tid);
  __syncthreads();                      // prior readers of wbuf are done
  int cur = 0;
#pragma unroll 1
  for (int t8 = 0; t8 < 8; ++t8) {
    stage_sts(r, wbuf + cur * (G4 * WSTR), tid);
    __syncthreads();
    if (t8 < 7) stage_ldg(r, Wg, (t8 + 1) * KT, tid);   // overlap next tile
    const float* wb = wbuf + cur * (G4 * WSTR);
    const int k0 = t8 * KT;
#pragma unroll
    for (int c = 0; c < KT; ++c) {
      const float* hrow = srcT + (k0 + c) * HSTR + s0;
      ulonglong2 a0 = *reinterpret_cast<const ulonglong2*>(hrow);
      ulonglong2 a1 = *reinterpret_cast<const ulonglong2*>(hrow + 4);
      ulonglong2 a2 = *reinterpret_cast<const ulonglong2*>(hrow + 8);
      ulonglong2 a3 = *reinterpret_cast<const ulonglong2*>(hrow + 12);
      ull hp0 = a0.x, hp1 = a0.y, hp2 = a1.x, hp3 = a1.y;
      ull hp4 = a2.x, hp5 = a2.y, hp6 = a3.x, hp7 = a3.y;
#pragma unroll
      for (int g = 0; g < 4; ++g) {
        ull w = pack2(wb[(j + (g << 7)) * WSTR + c]);
        ffma2(acc[g][0], w, hp0); ffma2(acc[g][1], w, hp1);
        ffma2(acc[g][2], w, hp2); ffma2(acc[g][3], w, hp3);
        ffma2(acc[g][4], w, hp4); ffma2(acc[g][5], w, hp5);
        ffma2(acc[g][6], w, hp6); ffma2(acc[g][7], w, hp7);
      }
    }
    cur ^= 1;
  }
}

// small input contribution (nf features) from transposed xT using packed pairs
__device__ __forceinline__ void accum_small(ull (&acc)[4][8],
                                            const float* __restrict__ wsm, int wstr,
                                            const float* __restrict__ xT, int nf,
                                            int j, int s0) {
  for (int i = 0; i < nf; ++i) {
    const float* xrow = xT + i * S_TILE + s0;
    ulonglong2 a0 = *reinterpret_cast<const ulonglong2*>(xrow);
    ulonglong2 a1 = *reinterpret_cast<const ulonglong2*>(xrow + 4);
    ulonglong2 a2 = *reinterpret_cast<const ulonglong2*>(xrow + 8);
    ulonglong2 a3 = *reinterpret_cast<const ulonglong2*>(xrow + 12);
    ull hp[8] = {a0.x, a0.y, a1.x, a1.y, a2.x, a2.y, a3.x, a3.y};
#pragma unroll
    for (int g = 0; g < 4; ++g) {
      ull w = pack2(wsm[(j + (g << 7)) * wstr + i]);
#pragma unroll
      for (int p = 0; p < 8; ++p) ffma2(acc[g][p], w, hp[p]);
    }
  }
}

__device__ __forceinline__ void cell_update(ull (&acc)[4][8], float* cr, float* hnew) {
#pragma unroll
  for (int p = 0; p < 8; ++p) {
    float i0, i1, f0, f1, g0, g1, o0, o1;
    unpack2(acc[0][p], i0, i1);
    unpack2(acc[1][p], f0, f1);
    unpack2(acc[2][p], g0, g1);
    unpack2(acc[3][p], o0, o1);
    float c0 = sigmoidf_(f0) * cr[2 * p]     + sigmoidf_(i0) * tanhf_(g0);
    float c1 = sigmoidf_(f1) * cr[2 * p + 1] + sigmoidf_(i1) * tanhf_(g1);
    cr[2 * p]     = c0;
    cr[2 * p + 1] = c1;
    hnew[2 * p]     = sigmoidf_(o0) * tanhf_(c0);
    hnew[2 * p + 1] = sigmoidf_(o1) * tanhf_(c1);
  }
}

__device__ __forceinline__ void write_h(float* hT, const float* hnew, int j, int s0) {
  float* base = hT + j * HSTR + s0;
#pragma unroll
  for (int m = 0; m < 4; ++m) {
    *reinterpret_cast<float4*>(base + 4 * m) =
        make_float4(hnew[4 * m], hnew[4 * m + 1], hnew[4 * m + 2], hnew[4 * m + 3]);
  }
}

__global__ void __launch_bounds__(THREADS)
lstm_seq2seq_kernel(const float* __restrict__ history,
                    const float* __restrict__ start_token,
                    const float* __restrict__ eWih0, const float* __restrict__ eWhh0,
                    const float* __restrict__ eb0,
                    const float* __restrict__ eWih1, const float* __restrict__ eWhh1,
                    const float* __restrict__ eb1,
                    const float* __restrict__ dWih0, const float* __restrict__ dWhh0,
                    const float* __restrict__ db0,
                    const float* __restrict__ dWih1, const float* __restrict__ dWhh1,
                    const float* __restrict__ db1,
                    const float* __restrict__ outW, const float* __restrict__ outb,
                    float* __restrict__ out) {
  extern __shared__ float smraw[];
  Smem& s = *reinterpret_cast<Smem*>(smraw);

  const int tid = threadIdx.x;
  const int j   = tid & 127;
  const int s0  = (tid >> 7) * SG;
  const int b0  = blockIdx.x * S_TILE;

  // ---- one-time SMEM setup ----
  for (int idx = tid; idx < G4 * INF; idx += THREADS) {
    int r = idx / INF, c = idx % INF;
    s.wih0e[r * 8 + c] = eWih0[idx];
  }
  for (int idx = tid; idx < G4 * OUTF; idx += THREADS) {
    int r = idx >> 1, c = idx & 1;
    s.wih0d[r * 4 + c] = dWih0[idx];
  }
  for (int idx = tid; idx < 2 * H; idx += THREADS) s.outW[idx] = outW[idx];
  for (int idx = tid; idx < G4; idx += THREADS) {
    s.b[idx]          = eb0[idx];
    s.b[G4 + idx]     = eb1[idx];
    s.b[2 * G4 + idx] = db0[idx];
    s.b[3 * G4 + idx] = db1[idx];
  }
  if (tid < 2) { s.outb[tid] = outb[tid]; s.st[tid] = start_token[tid]; }
  for (int idx = tid; idx < H * HSTR; idx += THREADS) { s.hT0[idx] = 0.0f; s.hT1[idx] = 0.0f; }

  float c0r[SG], c1r[SG];
#pragma unroll
  for (int k = 0; k < SG; ++k) { c0r[k] = 0.0f; c1r[k] = 0.0f; }

  ull  acc[4][8];
  float hnew[SG];

  __syncthreads();

  // ================= ENCODER =================
  for (int t = 0; t < T_HIST; ++t) {
    if (tid < S_TILE * INF) {
      int ss = tid / INF, i = tid % INF;
      s.xT[i * S_TILE + ss] =
          history[(((size_t)(b0 + ss) * A_ + 0) * T_HIST + t) * INF + i];
    }
    __syncthreads();

    // layer 0
    init_acc(acc, &s.b[0], j);
    accum_small(acc, s.wih0e, 8, s.xT, INF, j, s0);
    accum128(acc, eWhh0, s.hT0, s.w2, j, s0, tid);
    cell_update(acc, c0r, hnew);
    __syncthreads();                 // readers of old hT0 done
    write_h(s.hT0, hnew, j, s0);
    __syncthreads();

    // layer 1
    init_acc(acc, &s.b[G4], j);
    accum128(acc, eWih1, s.hT0, s.w2, j, s0, tid);
    accum128(acc, eWhh1, s.hT1, s.w2, j, s0, tid);
    cell_update(acc, c1r, hnew);
    __syncthreads();
    write_h(s.hT1, hnew, j, s0);
    __syncthreads();
  }

  // decoder start token
  if (tid < S_TILE * OUTF) {
    int ss = tid >> 1, o = tid & 1;
    s.xT[o * S_TILE + ss] = s.st[o];
  }
  __syncthreads();

  // ================= DECODER =================
  for (int t = 0; t < T_OUT; ++t) {
    // layer 0
    init_acc(acc, &s.b[2 * G4], j);
    accum_small(acc, s.wih0d, 4, s.xT, OUTF, j, s0);
    accum128(acc, dWhh0, s.hT0, s.w2, j, s0, tid);
    cell_update(acc, c0r, hnew);
    __syncthreads();
    write_h(s.hT0, hnew, j, s0);
    __syncthreads();

    // layer 1
    init_acc(acc, &s.b[3 * G4], j);
    accum128(acc, dWih1, s.hT0, s.w2, j, s0, tid);
    accum128(acc, dWhh1, s.hT1, s.w2, j, s0, tid);
    cell_update(acc, c1r, hnew);
    __syncthreads();
    write_h(s.hT1, hnew, j, s0);
    __syncthreads();

    // projection + feedback
    if (tid < S_TILE * OUTF) {
      int ss = tid >> 1, o = tid & 1;
      float a = s.outb[o];
      const float* wrow = &s.outW[o * H];
#pragma unroll 16
      for (int k = 0; k < H; ++k) a = fmaf(wrow[k], s.hT1[k * HSTR + ss], a);
      out[((size_t)(b0 + ss) * T_OUT + t) * OUTF + o] = a;
      s.xT[o * S_TILE + ss] = a;
    }
    __syncthreads();
  }
}

extern "C" void kernel_launch(void* const* d_in, const int* in_sizes, int n_in,
                              void* d_out, int out_size) {
  const float* history     = (const float*)d_in[0];
  const float* start_token = (const float*)d_in[1];
  const float* eWih0       = (const float*)d_in[2];
  const float* eWhh0       = (const float*)d_in[3];
  const float* eb0         = (const float*)d_in[4];
  const float* eWih1       = (const float*)d_in[5];
  const float* eWhh1       = (const float*)d_in[6];
  const float* eb1         = (const float*)d_in[7];
  const float* dWih0       = (const float*)d_in[8];
  const float* dWhh0       = (const float*)d_in[9];
  const float* db0         = (const float*)d_in[10];
  const float* dWih1       = (const float*)d_in[11];
  const float* dWhh1       = (const float*)d_in[12];
  const float* db1         = (const float*)d_in[13];
  const float* outW        = (const float*)d_in[14];
  const float* outb        = (const float*)d_in[15];
  float* out               = (float*)d_out;

  (void)in_sizes; (void)n_in; (void)out_size;

  cudaFuncSetAttribute(lstm_seq2seq_kernel,
                       cudaFuncAttributeMaxDynamicSharedMemorySize,
                       (int)sizeof(Smem));

  dim3 grid(B_ / S_TILE);   // 512 CTAs
  lstm_seq2seq_kernel<<<grid, THREADS, sizeof(Smem)>>>(
      history, start_token,
      eWih0, eWhh0, eb0, eWih1, eWhh1, eb1,
      dWih0, dWhh0, db0, dWih1, dWhh1, db1,
      outW, outb, out);
}